// round 14
// baseline (speedup 1.0000x reference)
#include <cuda_runtime.h>
#include <cuda_fp16.h>
#include <cstdint>

// ---------------------------------------------------------------------------
// HybridBlock: RMS -> merged{k,v,r} GEMM -> RWKV chunked scan -> o-GEMM(+res)
//              -> RMS -> fc-GEMM(leaky^2) -> mlp-GEMM(+res)
// GEMMs: mma.sync.m16n8k16 fp16 (fp32 accum), CTA tile 128x256 (8 warps,
// warp tile 64x64), K-tile 64, cp.async 3-stage x 48KB ring, 1 CTA/SM.
// Scan: CH_L=32 (512-CTA parallelism), fp16 k/v/r.
// ---------------------------------------------------------------------------

#define S_LEN 4096
#define B_SZ  4
#define D_DIM 1024
#define H_DIM 4096
#define M_ROWS (B_SZ * S_LEN)      // 16384
#define CH_L  32
#define CH_C  (S_LEN / CH_L)       // 128

// Scratch (device globals: allocation-free per harness rules)
__device__ __half g_normed[(size_t)M_ROWS * D_DIM];
__device__ __half g_k[(size_t)M_ROWS * D_DIM];
__device__ __half g_v[(size_t)M_ROWS * D_DIM];
__device__ __half g_r[(size_t)M_ROWS * D_DIM];
__device__ __half g_a[(size_t)M_ROWS * D_DIM];
__device__ float  g_x1[(size_t)M_ROWS * D_DIM];
__device__ __half g_h2[(size_t)M_ROWS * H_DIM];
__device__ float  g_carry[CH_C * B_SZ * D_DIM];
__device__ float  g_entry[CH_C * B_SZ * D_DIM];
__device__ __half g_wh[(size_t)12 * 1024 * 1024];   // fp16 weights

__device__ __forceinline__ uint32_t smem_to_u32(const void* p) {
    uint32_t a;
    asm("{ .reg .u64 t; cvta.to.shared.u64 t, %1; cvt.u32.u64 %0, t; }"
        : "=r"(a) : "l"(p));
    return a;
}

#define CP_ASYNC16(dst, src) \
    asm volatile("cp.async.cg.shared.global [%0], [%1], 16;" \
                 :: "r"(dst), "l"(src) : "memory")
#define CP_COMMIT() asm volatile("cp.async.commit_group;" ::: "memory")
#define CP_WAIT1()  asm volatile("cp.async.wait_group 1;" ::: "memory")

#define LDS128(r0, r1, r2, r3, addr) \
    asm volatile("ld.shared.v4.b32 {%0,%1,%2,%3}, [%4];" \
                 : "=r"(r0), "=r"(r1), "=r"(r2), "=r"(r3) : "r"(addr))

#define MMA_F16(d, a0, a1, a2, a3, b0, b1) \
    asm volatile( \
        "mma.sync.aligned.m16n8k16.row.col.f32.f16.f16.f32 " \
        "{%0,%1,%2,%3}, {%4,%5,%6,%7}, {%8,%9}, {%0,%1,%2,%3};\n" \
        : "+f"((d)[0]), "+f"((d)[1]), "+f"((d)[2]), "+f"((d)[3]) \
        : "r"(a0), "r"(a1), "r"(a2), "r"(a3), "r"(b0), "r"(b1))

// ---------------------------------------------------------------------------
// Weight convert fp32 -> fp16, all 6 weights, 4 float4/thread (MLP=4).
// g_wh layout: [Wk 1M][Wv 1M][Wr 1M][Wo 1M][Wfc 4M][Wmlp 4M] (floats count)
// ---------------------------------------------------------------------------
__global__ void cvt_all_kernel(const float* __restrict__ Wk, const float* __restrict__ Wv,
                               const float* __restrict__ Wr, const float* __restrict__ Wo,
                               const float* __restrict__ Wfc, const float* __restrict__ Wmlp) {
    const int M1 = 1024 * 1024 / 4;
    const size_t blk = (size_t)blockIdx.x * 1024 + threadIdx.x;
    #pragma unroll
    for (int j = 0; j < 4; j++) {
        const size_t i = blk + (size_t)j * 256;       // coalesced per j-step
        const float* src;
        size_t li;
        if (i < 4 * M1) { src = (i < M1) ? Wk : (i < 2 * M1) ? Wv : (i < 3 * M1) ? Wr : Wo;
                          li = i & (M1 - 1); }
        else if (i < 8 * M1) { src = Wfc;  li = i - 4 * M1; }
        else                 { src = Wmlp; li = i - 8 * M1; }
        const float4 v = reinterpret_cast<const float4*>(src)[li];
        const __half2 h0 = __floats2half2_rn(v.x, v.y);
        const __half2 h1 = __floats2half2_rn(v.z, v.w);
        uint2 u;
        u.x = *reinterpret_cast<const uint32_t*>(&h0);
        u.y = *reinterpret_cast<const uint32_t*>(&h1);
        reinterpret_cast<uint2*>(g_wh)[i] = u;
    }
}

// ---------------------------------------------------------------------------
// RMS norm: warp per row, output fp16.
// ---------------------------------------------------------------------------
__global__ void rms_kernel(const float* __restrict__ x, __half* __restrict__ out) {
    const int w = threadIdx.x >> 5, lid = threadIdx.x & 31;
    const int row = blockIdx.x * 8 + w;
    const float4* xr = reinterpret_cast<const float4*>(x + (size_t)row * D_DIM);
    float4 va[8];
    float ss = 0.f;
    #pragma unroll
    for (int i = 0; i < 8; i++) {
        va[i] = xr[lid + 32 * i];
        ss += va[i].x * va[i].x + va[i].y * va[i].y + va[i].z * va[i].z + va[i].w * va[i].w;
    }
    #pragma unroll
    for (int o = 16; o > 0; o >>= 1) ss += __shfl_xor_sync(0xffffffffu, ss, o);
    const float inv = rsqrtf(ss * (1.0f / (float)D_DIM) + 1e-6f);
    uint2* orow = reinterpret_cast<uint2*>(out + (size_t)row * D_DIM);
    #pragma unroll
    for (int i = 0; i < 8; i++) {
        const __half2 h0 = __floats2half2_rn(va[i].x * inv, va[i].y * inv);
        const __half2 h1 = __floats2half2_rn(va[i].z * inv, va[i].w * inv);
        uint2 u;
        u.x = *reinterpret_cast<const uint32_t*>(&h0);
        u.y = *reinterpret_cast<const uint32_t*>(&h1);
        orow[lid + 32 * i] = u;
    }
}

// ---------------------------------------------------------------------------
// RWKV chunked scan: k,v,r fp16 inputs, fp32 state (exact factorization).
// 4 channels/thread (uint2 = 4 halfs per load). CH_L=32 -> 512-CTA phases.
// ---------------------------------------------------------------------------
#define D4 (D_DIM / 4)   // 256

__device__ __forceinline__ float4 h4_to_f4(uint2 u) {
    const __half2 a = *reinterpret_cast<const __half2*>(&u.x);
    const __half2 b = *reinterpret_cast<const __half2*>(&u.y);
    const float2 fa = __half22float2(a);
    const float2 fb = __half22float2(b);
    return make_float4(fa.x, fa.y, fb.x, fb.y);
}

__global__ void scan_carry(const __half* __restrict__ k, const __half* __restrict__ v,
                           const float* __restrict__ td) {
    const int d4 = threadIdx.x;           // 0..255
    const int c = blockIdx.y, b = blockIdx.z;
    const float4 t4 = reinterpret_cast<const float4*>(td)[d4];
    float4 ew;
    ew.x = expf(-expf(t4.x)); ew.y = expf(-expf(t4.y));
    ew.z = expf(-expf(t4.z)); ew.w = expf(-expf(t4.w));
    const uint2* k4 = reinterpret_cast<const uint2*>(k);
    const uint2* v4 = reinterpret_cast<const uint2*>(v);
    size_t base = ((size_t)b * S_LEN + (size_t)c * CH_L) * D4 + d4;
    float4 cr = make_float4(0.f, 0.f, 0.f, 0.f);
    #pragma unroll 4
    for (int i = 0; i < CH_L; i++) {
        const float4 kk = h4_to_f4(k4[base]);
        const float4 vv = h4_to_f4(v4[base]);
        cr.x = ew.x * cr.x + kk.x * vv.x;
        cr.y = ew.y * cr.y + kk.y * vv.y;
        cr.z = ew.z * cr.z + kk.z * vv.z;
        cr.w = ew.w * cr.w + kk.w * vv.w;
        base += D4;
    }
    reinterpret_cast<float4*>(g_carry)[((size_t)c * B_SZ + b) * D4 + d4] = cr;
}

__global__ void scan_combine(const float* __restrict__ td) {
    const int d = blockIdx.x * 256 + threadIdx.x;
    const int b = blockIdx.y;
    const float ewL = expf(-(float)CH_L * expf(td[d]));
    float s = 0.f;
    #pragma unroll 8
    for (int c = 0; c < CH_C; c++) {
        const size_t idx = ((size_t)c * B_SZ + b) * D_DIM + d;
        g_entry[idx] = s;
        s = ewL * s + g_carry[idx];
    }
}

__global__ void scan_apply(const __half* __restrict__ k, const __half* __restrict__ v,
                           const __half* __restrict__ r,
                           const float* __restrict__ td, const float* __restrict__ tfirst) {
    const int d4 = threadIdx.x;
    const int c = blockIdx.y, b = blockIdx.z;
    const float4 t4 = reinterpret_cast<const float4*>(td)[d4];
    const float4 u4 = reinterpret_cast<const float4*>(tfirst)[d4];
    float4 ew, eu;
    ew.x = expf(-expf(t4.x)); ew.y = expf(-expf(t4.y));
    ew.z = expf(-expf(t4.z)); ew.w = expf(-expf(t4.w));
    eu.x = expf(u4.x); eu.y = expf(u4.y); eu.z = expf(u4.z); eu.w = expf(u4.w);
    float4 s = reinterpret_cast<const float4*>(g_entry)[((size_t)c * B_SZ + b) * D4 + d4];
    const uint2* k4 = reinterpret_cast<const uint2*>(k);
    const uint2* v4 = reinterpret_cast<const uint2*>(v);
    const uint2* r4 = reinterpret_cast<const uint2*>(r);
    uint2* a4 = reinterpret_cast<uint2*>(g_a);
    size_t base = ((size_t)b * S_LEN + (size_t)c * CH_L) * D4 + d4;
    #pragma unroll 4
    for (int i = 0; i < CH_L; i++) {
        const float4 kk = h4_to_f4(k4[base]);
        const float4 vv = h4_to_f4(v4[base]);
        const float4 rr = h4_to_f4(r4[base]);
        float4 kv;
        kv.x = kk.x * vv.x; kv.y = kk.y * vv.y; kv.z = kk.z * vv.z; kv.w = kk.w * vv.w;
        const __half2 h0 = __floats2half2_rn(rr.x * (s.x + eu.x * kv.x),
                                             rr.y * (s.y + eu.y * kv.y));
        const __half2 h1 = __floats2half2_rn(rr.z * (s.z + eu.z * kv.z),
                                             rr.w * (s.w + eu.w * kv.w));
        uint2 u;
        u.x = *reinterpret_cast<const uint32_t*>(&h0);
        u.y = *reinterpret_cast<const uint32_t*>(&h1);
        a4[base] = u;
        s.x = ew.x * s.x + kv.x; s.y = ew.y * s.y + kv.y;
        s.z = ew.z * s.z + kv.z; s.w = ew.w * s.w + kv.w;
        base += D4;
    }
}

// ---------------------------------------------------------------------------
// fp16 mma.sync GEMM: C[M,N] = A[M,K] @ B[N,K]^T (A,B fp16, fp32 accum).
// CTA tile 128x256, 256 threads, 8 warps (2x4), warp tile 64x64, K-tile 64.
// Stage = A 16KB + B 32KB = 48KB; 3-stage ring (144KB), 1 CTA/SM.
// Per-warp MMA K-order identical to the 128x128 version (bit-identical).
// EPI: 2=res+scale*acc (f32 out) 3=(leaky0.5)^2 (fp16 out)
//      4=merged-kvr (fp16 out; seg2=sigmoid)
// ---------------------------------------------------------------------------
#define NST 3
#define A_BYTES 16384
#define STAGE_BYTES 49152    // A 16KB + B 32KB
#define SMEM_TOTAL (NST * STAGE_BYTES)   // 147456

template <int EPI>
__global__ void __launch_bounds__(256, 1) gemm_h(
    const __half* __restrict__ A, const __half* __restrict__ Bw,
    void* __restrict__ Cout, int K, int N,
    const void* __restrict__ res, const void* __restrict__ scale)
{
    extern __shared__ char smem[];
    const uint32_t sb = smem_to_u32(smem);
    const int tid = threadIdx.x;
    const int bn = blockIdx.x, bm = blockIdx.y;
    const int warp = tid >> 5, lane = tid & 31;
    const int wm = warp >> 2, wn = warp & 3;      // 2x4 warp grid, 64x64 tiles
    const int gid = lane >> 2, tig = lane & 3;

    const __half* Ab = A + (size_t)bm * 128 * K;
    const __half* Bb = Bw + (size_t)bn * 256 * K;

    // cp.async: thread covers row (tid>>3)+32j, halfs [(tid&7)*8 .. +8).
    // A: j=0..3 (128 rows); B: j=0..7 (256 rows). 16B per chunk.
    const __half* gA = Ab + (size_t)(tid >> 3) * K + (tid & 7) * 8;
    const __half* gB = Bb + (size_t)(tid >> 3) * K + (tid & 7) * 8;
    const uint32_t dA = sb + tid * 16;
    const uint32_t dB = sb + A_BYTES + tid * 16;
    const size_t rowstr = (size_t)32 * K;    // 32 rows per j step

    float acc[4][8][4];
    #pragma unroll
    for (int i = 0; i < 4; i++)
        #pragma unroll
        for (int j = 0; j < 8; j++)
            #pragma unroll
            for (int l = 0; l < 4; l++) acc[i][j][l] = 0.f;

    const int KT = K >> 6;     // 64 halfs per K-tile

#define LOAD_STAGE(s, kt) do { \
    const uint32_t so_ = (uint32_t)(s) * STAGE_BYTES; \
    const __half* a_ = gA + (kt) * 64; \
    const __half* b_ = gB + (kt) * 64; \
    _Pragma("unroll") \
    for (int j = 0; j < 4; j++) \
        CP_ASYNC16(dA + so_ + j * 4096, a_ + j * rowstr); \
    _Pragma("unroll") \
    for (int j = 0; j < 8; j++) \
        CP_ASYNC16(dB + so_ + j * 4096, b_ + j * rowstr); \
    CP_COMMIT(); \
} while (0)

    LOAD_STAGE(0, 0);
    LOAD_STAGE(1, 1);

    const uint32_t a_base = sb + (uint32_t)(wm * 64 + gid) * 128 + tig * 16;
    const uint32_t b_base = sb + A_BYTES + (uint32_t)(wn * 64 + gid) * 128 + tig * 16;

    int s_cur = 0, s_pre = 2;
    for (int kt = 0; kt < KT; kt++) {
        CP_WAIT1();
        __syncthreads();

        if (kt + 2 < KT) LOAD_STAGE(s_pre, kt + 2);

        const uint32_t so = (uint32_t)s_cur * STAGE_BYTES;
        #pragma unroll
        for (int g = 0; g < 2; g++) {            // k-groups in ascending k order
            const uint32_t go = so + g * 64;
            uint32_t bf[8][4];
            #pragma unroll
            for (int ni = 0; ni < 8; ni++)
                LDS128(bf[ni][0], bf[ni][1], bf[ni][2], bf[ni][3],
                       b_base + go + ni * 1024);
            #pragma unroll
            for (int mi = 0; mi < 4; mi++) {
                uint32_t lo0, lo1, lo2, lo3, hi0, hi1, hi2, hi3;
                LDS128(lo0, lo1, lo2, lo3, a_base + go + mi * 2048);
                LDS128(hi0, hi1, hi2, hi3, a_base + go + mi * 2048 + 1024);
                #pragma unroll
                for (int ni = 0; ni < 8; ni++) {
                    MMA_F16(acc[mi][ni], lo0, hi0, lo1, hi1, bf[ni][0], bf[ni][1]);
                    MMA_F16(acc[mi][ni], lo2, hi2, lo3, hi3, bf[ni][2], bf[ni][3]);
                }
            }
        }

        if (++s_cur == NST) s_cur = 0;
        if (++s_pre == NST) s_pre = 0;
    }

    // epilogue
    float* Cf = (float*)Cout;
    __half* Ch = (__half*)Cout;
    int seg = 0, Nout = N, col_base = bn * 256;
    if (EPI == 4) {
        seg = bn >> 2;                            // 256-col tiles, 4 per segment
        Ch = (seg == 0) ? (__half*)Cout : (seg == 1) ? (__half*)res : (__half*)scale;
        Nout = D_DIM;
        col_base = (bn & 3) * 256;
    }
    const int row0 = bm * 128 + wm * 64 + gid;
    const int col0 = col_base + wn * 64 + 2 * tig;
    #pragma unroll
    for (int mi = 0; mi < 4; mi++) {
        #pragma unroll
        for (int ni = 0; ni < 8; ni++) {
            const int gc = col0 + ni * 8;
            #pragma unroll
            for (int h = 0; h < 2; h++) {
                const int gr = row0 + mi * 16 + h * 8;
                float v0 = acc[mi][ni][2 * h + 0];
                float v1 = acc[mi][ni][2 * h + 1];
                if (EPI == 2) {
                    const float2 rr = *reinterpret_cast<const float2*>(
                        (const float*)res + (size_t)gr * N + gc);
                    const float2 sc = *reinterpret_cast<const float2*>(
                        (const float*)scale + gc);
                    *reinterpret_cast<float2*>(Cf + (size_t)gr * N + gc) =
                        make_float2(rr.x + sc.x * v0, rr.y + sc.y * v1);
                } else if (EPI == 3) {
                    const float t0 = v0 > 0.f ? v0 : 0.5f * v0;
                    const float t1 = v1 > 0.f ? v1 : 0.5f * v1;
                    const __half2 hv = __floats2half2_rn(t0 * t0, t1 * t1);
                    *reinterpret_cast<__half2*>(Ch + (size_t)gr * N + gc) = hv;
                } else if (EPI == 4) {
                    if (seg == 2) {
                        v0 = 1.f / (1.f + expf(-v0));
                        v1 = 1.f / (1.f + expf(-v1));
                    }
                    const __half2 hv = __floats2half2_rn(v0, v1);
                    *reinterpret_cast<__half2*>(Ch + (size_t)gr * Nout + gc) = hv;
                }
            }
        }
    }
#undef LOAD_STAGE
}

// ---------------------------------------------------------------------------
// Launch
// ---------------------------------------------------------------------------
extern "C" void kernel_launch(void* const* d_in, const int* in_sizes, int n_in,
                              void* d_out, int out_size) {
    const float* x     = (const float*)d_in[0];
    const float* Wk    = (const float*)d_in[1];
    const float* Wv    = (const float*)d_in[2];
    const float* Wr    = (const float*)d_in[3];
    const float* Wo    = (const float*)d_in[4];
    const float* td    = (const float*)d_in[5];
    const float* tfst  = (const float*)d_in[6];
    const float* mscl  = (const float*)d_in[7];
    const float* Wfc   = (const float*)d_in[8];
    const float* Wmlp  = (const float*)d_in[9];
    const float* pscl  = (const float*)d_in[10];
    float* out = (float*)d_out;

    float *p_x1;
    __half *p_normed, *p_k, *p_v, *p_r, *p_a, *p_h2, *p_w;
    cudaGetSymbolAddress((void**)&p_normed, g_normed);
    cudaGetSymbolAddress((void**)&p_k, g_k);
    cudaGetSymbolAddress((void**)&p_v, g_v);
    cudaGetSymbolAddress((void**)&p_r, g_r);
    cudaGetSymbolAddress((void**)&p_a, g_a);
    cudaGetSymbolAddress((void**)&p_x1, g_x1);
    cudaGetSymbolAddress((void**)&p_h2, g_h2);
    cudaGetSymbolAddress((void**)&p_w, g_wh);

    __half* cWkvr = p_w;                                  // [3072,1024]
    __half* cWo   = p_w + (size_t)3 * 1024 * 1024;
    __half* cWfc  = p_w + (size_t)4 * 1024 * 1024;
    __half* cWmlp = p_w + (size_t)8 * 1024 * 1024;

    cudaFuncSetAttribute(gemm_h<2>, cudaFuncAttributeMaxDynamicSharedMemorySize, SMEM_TOTAL);
    cudaFuncSetAttribute(gemm_h<3>, cudaFuncAttributeMaxDynamicSharedMemorySize, SMEM_TOTAL);
    cudaFuncSetAttribute(gemm_h<4>, cudaFuncAttributeMaxDynamicSharedMemorySize, SMEM_TOTAL);

    const dim3 gemmD(D_DIM / 256, M_ROWS / 128);        // (4, 128)
    const dim3 gemmKVR(3 * D_DIM / 256, M_ROWS / 128);  // (12, 128)
    const dim3 gemmH(H_DIM / 256, M_ROWS / 128);        // (16, 128)

    // 0) weights -> fp16 (one launch, 4 float4/thread)
    cvt_all_kernel<<<(12 * 1024 * 1024 / 4) / 1024, 256>>>(Wk, Wv, Wr, Wo, Wfc, Wmlp);
    // 1) RMS(x) -> fp16
    rms_kernel<<<M_ROWS / 8, 256>>>(x, p_normed);
    // 2) merged k|v|r GEMM (fp16 outputs)
    gemm_h<4><<<gemmKVR, 256, SMEM_TOTAL>>>(p_normed, cWkvr, p_k, D_DIM, 3 * D_DIM, p_v, p_r);
    // 3) chunked RWKV scan (fp32 state), fuse r*wkv into g_a (fp16)
    scan_carry<<<dim3(1, CH_C, B_SZ), 256>>>(p_k, p_v, td);
    scan_combine<<<dim3(D_DIM / 256, B_SZ), 256>>>(td);
    scan_apply<<<dim3(1, CH_C, B_SZ), 256>>>(p_k, p_v, p_r, td, tfst);
    // 4) o-GEMM + residual -> x1 (f32)
    gemm_h<2><<<gemmD, 256, SMEM_TOTAL>>>(p_a, cWo, p_x1, D_DIM, D_DIM, x, mscl);
    // 5) RMS(x1) -> fp16
    rms_kernel<<<M_ROWS / 8, 256>>>(p_x1, p_normed);
    // 6) fc-GEMM with leaky(0.5)^2 epilogue -> h2 (fp16)
    gemm_h<3><<<gemmH, 256, SMEM_TOTAL>>>(p_normed, cWfc, p_h2, D_DIM, H_DIM, nullptr, nullptr);
    // 7) mlp-GEMM + residual -> out (f32)
    gemm_h<2><<<gemmD, 256, SMEM_TOTAL>>>(p_h2, cWmlp, out, H_DIM, D_DIM, p_x1, pscl);
}

// round 15
// speedup vs baseline: 1.1643x; 1.1643x over previous
#include <cuda_runtime.h>
#include <cuda_fp16.h>
#include <cstdint>

// ---------------------------------------------------------------------------
// HybridBlock: RMS -> merged{k,v,r} GEMM -> RWKV chunked scan -> o-GEMM(+res)
//              -> RMS -> fc-GEMM(leaky^2) -> mlp-GEMM(+res)
// GEMMs: mma.sync.m16n8k16 fp16 (fp32 accum), CTA tile 128x128 (4 warps,
// warp tile 64x64), K-tile 64, cp.async 3-stage x 32KB ring, 2 CTAs/SM.
// Scan: CH_L=32 (512-CTA parallelism), fp16 k/v/r.
// ---------------------------------------------------------------------------

#define S_LEN 4096
#define B_SZ  4
#define D_DIM 1024
#define H_DIM 4096
#define M_ROWS (B_SZ * S_LEN)      // 16384
#define CH_L  32
#define CH_C  (S_LEN / CH_L)       // 128

// Scratch (device globals: allocation-free per harness rules)
__device__ __half g_normed[(size_t)M_ROWS * D_DIM];
__device__ __half g_k[(size_t)M_ROWS * D_DIM];
__device__ __half g_v[(size_t)M_ROWS * D_DIM];
__device__ __half g_r[(size_t)M_ROWS * D_DIM];
__device__ __half g_a[(size_t)M_ROWS * D_DIM];
__device__ float  g_x1[(size_t)M_ROWS * D_DIM];
__device__ __half g_h2[(size_t)M_ROWS * H_DIM];
__device__ float  g_carry[CH_C * B_SZ * D_DIM];
__device__ float  g_entry[CH_C * B_SZ * D_DIM];
__device__ __half g_wh[(size_t)12 * 1024 * 1024];   // fp16 weights

__device__ __forceinline__ uint32_t smem_to_u32(const void* p) {
    uint32_t a;
    asm("{ .reg .u64 t; cvta.to.shared.u64 t, %1; cvt.u32.u64 %0, t; }"
        : "=r"(a) : "l"(p));
    return a;
}

#define CP_ASYNC16(dst, src) \
    asm volatile("cp.async.cg.shared.global [%0], [%1], 16;" \
                 :: "r"(dst), "l"(src) : "memory")
#define CP_COMMIT() asm volatile("cp.async.commit_group;" ::: "memory")
#define CP_WAIT1()  asm volatile("cp.async.wait_group 1;" ::: "memory")

#define LDS128(r0, r1, r2, r3, addr) \
    asm volatile("ld.shared.v4.b32 {%0,%1,%2,%3}, [%4];" \
                 : "=r"(r0), "=r"(r1), "=r"(r2), "=r"(r3) : "r"(addr))

#define MMA_F16(d, a0, a1, a2, a3, b0, b1) \
    asm volatile( \
        "mma.sync.aligned.m16n8k16.row.col.f32.f16.f16.f32 " \
        "{%0,%1,%2,%3}, {%4,%5,%6,%7}, {%8,%9}, {%0,%1,%2,%3};\n" \
        : "+f"((d)[0]), "+f"((d)[1]), "+f"((d)[2]), "+f"((d)[3]) \
        : "r"(a0), "r"(a1), "r"(a2), "r"(a3), "r"(b0), "r"(b1))

// ---------------------------------------------------------------------------
// Weight convert fp32 -> fp16, all 6 weights, 4 float4/thread (MLP=4).
// g_wh layout: [Wk 1M][Wv 1M][Wr 1M][Wo 1M][Wfc 4M][Wmlp 4M] (floats count)
// ---------------------------------------------------------------------------
__global__ void cvt_all_kernel(const float* __restrict__ Wk, const float* __restrict__ Wv,
                               const float* __restrict__ Wr, const float* __restrict__ Wo,
                               const float* __restrict__ Wfc, const float* __restrict__ Wmlp) {
    const int M1 = 1024 * 1024 / 4;
    const size_t blk = (size_t)blockIdx.x * 1024 + threadIdx.x;
    #pragma unroll
    for (int j = 0; j < 4; j++) {
        const size_t i = blk + (size_t)j * 256;       // coalesced per j-step
        const float* src;
        size_t li;
        if (i < 4 * M1) { src = (i < M1) ? Wk : (i < 2 * M1) ? Wv : (i < 3 * M1) ? Wr : Wo;
                          li = i & (M1 - 1); }
        else if (i < 8 * M1) { src = Wfc;  li = i - 4 * M1; }
        else                 { src = Wmlp; li = i - 8 * M1; }
        const float4 v = reinterpret_cast<const float4*>(src)[li];
        const __half2 h0 = __floats2half2_rn(v.x, v.y);
        const __half2 h1 = __floats2half2_rn(v.z, v.w);
        uint2 u;
        u.x = *reinterpret_cast<const uint32_t*>(&h0);
        u.y = *reinterpret_cast<const uint32_t*>(&h1);
        reinterpret_cast<uint2*>(g_wh)[i] = u;
    }
}

// ---------------------------------------------------------------------------
// RMS norm: warp per row, output fp16.
// ---------------------------------------------------------------------------
__global__ void rms_kernel(const float* __restrict__ x, __half* __restrict__ out) {
    const int w = threadIdx.x >> 5, lid = threadIdx.x & 31;
    const int row = blockIdx.x * 8 + w;
    const float4* xr = reinterpret_cast<const float4*>(x + (size_t)row * D_DIM);
    float4 va[8];
    float ss = 0.f;
    #pragma unroll
    for (int i = 0; i < 8; i++) {
        va[i] = xr[lid + 32 * i];
        ss += va[i].x * va[i].x + va[i].y * va[i].y + va[i].z * va[i].z + va[i].w * va[i].w;
    }
    #pragma unroll
    for (int o = 16; o > 0; o >>= 1) ss += __shfl_xor_sync(0xffffffffu, ss, o);
    const float inv = rsqrtf(ss * (1.0f / (float)D_DIM) + 1e-6f);
    uint2* orow = reinterpret_cast<uint2*>(out + (size_t)row * D_DIM);
    #pragma unroll
    for (int i = 0; i < 8; i++) {
        const __half2 h0 = __floats2half2_rn(va[i].x * inv, va[i].y * inv);
        const __half2 h1 = __floats2half2_rn(va[i].z * inv, va[i].w * inv);
        uint2 u;
        u.x = *reinterpret_cast<const uint32_t*>(&h0);
        u.y = *reinterpret_cast<const uint32_t*>(&h1);
        orow[lid + 32 * i] = u;
    }
}

// ---------------------------------------------------------------------------
// RWKV chunked scan: k,v,r fp16 inputs, fp32 state (exact factorization).
// 4 channels/thread (uint2 = 4 halfs per load). CH_L=32 -> 512-CTA phases.
// ---------------------------------------------------------------------------
#define D4 (D_DIM / 4)   // 256

__device__ __forceinline__ float4 h4_to_f4(uint2 u) {
    const __half2 a = *reinterpret_cast<const __half2*>(&u.x);
    const __half2 b = *reinterpret_cast<const __half2*>(&u.y);
    const float2 fa = __half22float2(a);
    const float2 fb = __half22float2(b);
    return make_float4(fa.x, fa.y, fb.x, fb.y);
}

__global__ void scan_carry(const __half* __restrict__ k, const __half* __restrict__ v,
                           const float* __restrict__ td) {
    const int d4 = threadIdx.x;           // 0..255
    const int c = blockIdx.y, b = blockIdx.z;
    const float4 t4 = reinterpret_cast<const float4*>(td)[d4];
    float4 ew;
    ew.x = expf(-expf(t4.x)); ew.y = expf(-expf(t4.y));
    ew.z = expf(-expf(t4.z)); ew.w = expf(-expf(t4.w));
    const uint2* k4 = reinterpret_cast<const uint2*>(k);
    const uint2* v4 = reinterpret_cast<const uint2*>(v);
    size_t base = ((size_t)b * S_LEN + (size_t)c * CH_L) * D4 + d4;
    float4 cr = make_float4(0.f, 0.f, 0.f, 0.f);
    #pragma unroll 4
    for (int i = 0; i < CH_L; i++) {
        const float4 kk = h4_to_f4(k4[base]);
        const float4 vv = h4_to_f4(v4[base]);
        cr.x = ew.x * cr.x + kk.x * vv.x;
        cr.y = ew.y * cr.y + kk.y * vv.y;
        cr.z = ew.z * cr.z + kk.z * vv.z;
        cr.w = ew.w * cr.w + kk.w * vv.w;
        base += D4;
    }
    reinterpret_cast<float4*>(g_carry)[((size_t)c * B_SZ + b) * D4 + d4] = cr;
}

__global__ void scan_combine(const float* __restrict__ td) {
    const int d = blockIdx.x * 256 + threadIdx.x;
    const int b = blockIdx.y;
    const float ewL = expf(-(float)CH_L * expf(td[d]));
    float s = 0.f;
    #pragma unroll 8
    for (int c = 0; c < CH_C; c++) {
        const size_t idx = ((size_t)c * B_SZ + b) * D_DIM + d;
        g_entry[idx] = s;
        s = ewL * s + g_carry[idx];
    }
}

__global__ void scan_apply(const __half* __restrict__ k, const __half* __restrict__ v,
                           const __half* __restrict__ r,
                           const float* __restrict__ td, const float* __restrict__ tfirst) {
    const int d4 = threadIdx.x;
    const int c = blockIdx.y, b = blockIdx.z;
    const float4 t4 = reinterpret_cast<const float4*>(td)[d4];
    const float4 u4 = reinterpret_cast<const float4*>(tfirst)[d4];
    float4 ew, eu;
    ew.x = expf(-expf(t4.x)); ew.y = expf(-expf(t4.y));
    ew.z = expf(-expf(t4.z)); ew.w = expf(-expf(t4.w));
    eu.x = expf(u4.x); eu.y = expf(u4.y); eu.z = expf(u4.z); eu.w = expf(u4.w);
    float4 s = reinterpret_cast<const float4*>(g_entry)[((size_t)c * B_SZ + b) * D4 + d4];
    const uint2* k4 = reinterpret_cast<const uint2*>(k);
    const uint2* v4 = reinterpret_cast<const uint2*>(v);
    const uint2* r4 = reinterpret_cast<const uint2*>(r);
    uint2* a4 = reinterpret_cast<uint2*>(g_a);
    size_t base = ((size_t)b * S_LEN + (size_t)c * CH_L) * D4 + d4;
    #pragma unroll 4
    for (int i = 0; i < CH_L; i++) {
        const float4 kk = h4_to_f4(k4[base]);
        const float4 vv = h4_to_f4(v4[base]);
        const float4 rr = h4_to_f4(r4[base]);
        float4 kv;
        kv.x = kk.x * vv.x; kv.y = kk.y * vv.y; kv.z = kk.z * vv.z; kv.w = kk.w * vv.w;
        const __half2 h0 = __floats2half2_rn(rr.x * (s.x + eu.x * kv.x),
                                             rr.y * (s.y + eu.y * kv.y));
        const __half2 h1 = __floats2half2_rn(rr.z * (s.z + eu.z * kv.z),
                                             rr.w * (s.w + eu.w * kv.w));
        uint2 u;
        u.x = *reinterpret_cast<const uint32_t*>(&h0);
        u.y = *reinterpret_cast<const uint32_t*>(&h1);
        a4[base] = u;
        s.x = ew.x * s.x + kv.x; s.y = ew.y * s.y + kv.y;
        s.z = ew.z * s.z + kv.z; s.w = ew.w * s.w + kv.w;
        base += D4;
    }
}

// ---------------------------------------------------------------------------
// fp16 mma.sync GEMM: C[M,N] = A[M,K] @ B[N,K]^T (A,B fp16, fp32 accum).
// Block 128x128xK64, 128 threads, 4 warps (2x2), warp tile 64x64.
// cp.async 3-stage x 32KB ring (96KB), 2 CTAs/SM.
// EPI: 2=res+scale*acc (f32 out) 3=(leaky0.5)^2 (fp16 out)
//      4=merged-kvr (fp16 out; seg2=sigmoid)
// ---------------------------------------------------------------------------
#define NST 3
#define STAGE_BYTES 32768    // A 16KB + B 16KB
#define SMEM_TOTAL (NST * STAGE_BYTES)

template <int EPI>
__global__ void __launch_bounds__(128, 2) gemm_h(
    const __half* __restrict__ A, const __half* __restrict__ Bw,
    void* __restrict__ Cout, int K, int N,
    const void* __restrict__ res, const void* __restrict__ scale)
{
    extern __shared__ char smem[];
    const uint32_t sb = smem_to_u32(smem);
    const int tid = threadIdx.x;
    const int bn = blockIdx.x, bm = blockIdx.y;
    const int warp = tid >> 5, lane = tid & 31;
    const int wm = warp >> 1, wn = warp & 1;      // 2x2 warp grid, 64x64 tiles
    const int gid = lane >> 2, tig = lane & 3;

    const __half* Ab = A + (size_t)bm * 128 * K;
    const __half* Bb = Bw + (size_t)bn * 128 * K;

    const __half* gA = Ab + (size_t)(tid >> 3) * K + (tid & 7) * 8;
    const __half* gB = Bb + (size_t)(tid >> 3) * K + (tid & 7) * 8;
    const uint32_t dA = sb + tid * 16;
    const uint32_t dB = sb + 16384 + tid * 16;
    const size_t rowstr = (size_t)16 * K;    // 16 rows per j step

    float acc[4][8][4];
    #pragma unroll
    for (int i = 0; i < 4; i++)
        #pragma unroll
        for (int j = 0; j < 8; j++)
            #pragma unroll
            for (int l = 0; l < 4; l++) acc[i][j][l] = 0.f;

    const int KT = K >> 6;     // 64 halfs per K-tile

#define LOAD_STAGE(s, kt) do { \
    const uint32_t so_ = (uint32_t)(s) * STAGE_BYTES; \
    const __half* a_ = gA + (kt) * 64; \
    const __half* b_ = gB + (kt) * 64; \
    _Pragma("unroll") \
    for (int j = 0; j < 8; j++) { \
        CP_ASYNC16(dA + so_ + j * 2048, a_ + j * rowstr); \
        CP_ASYNC16(dB + so_ + j * 2048, b_ + j * rowstr); \
    } \
    CP_COMMIT(); \
} while (0)

    LOAD_STAGE(0, 0);
    LOAD_STAGE(1, 1);

    const uint32_t a_base = sb + (uint32_t)(wm * 64 + gid) * 128 + tig * 16;
    const uint32_t b_base = sb + 16384 + (uint32_t)(wn * 64 + gid) * 128 + tig * 16;

    int s_cur = 0, s_pre = 2;
    for (int kt = 0; kt < KT; kt++) {
        CP_WAIT1();
        __syncthreads();

        if (kt + 2 < KT) LOAD_STAGE(s_pre, kt + 2);

        const uint32_t so = (uint32_t)s_cur * STAGE_BYTES;
        #pragma unroll
        for (int g = 0; g < 2; g++) {            // k-groups in ascending k order
            const uint32_t go = so + g * 64;
            uint32_t bf[8][4];
            #pragma unroll
            for (int ni = 0; ni < 8; ni++)
                LDS128(bf[ni][0], bf[ni][1], bf[ni][2], bf[ni][3],
                       b_base + go + ni * 1024);
            #pragma unroll
            for (int mi = 0; mi < 4; mi++) {
                uint32_t lo0, lo1, lo2, lo3, hi0, hi1, hi2, hi3;
                LDS128(lo0, lo1, lo2, lo3, a_base + go + mi * 2048);
                LDS128(hi0, hi1, hi2, hi3, a_base + go + mi * 2048 + 1024);
                #pragma unroll
                for (int ni = 0; ni < 8; ni++) {
                    MMA_F16(acc[mi][ni], lo0, hi0, lo1, hi1, bf[ni][0], bf[ni][1]);
                    MMA_F16(acc[mi][ni], lo2, hi2, lo3, hi3, bf[ni][2], bf[ni][3]);
                }
            }
        }

        if (++s_cur == NST) s_cur = 0;
        if (++s_pre == NST) s_pre = 0;
    }

    // epilogue
    float* Cf = (float*)Cout;
    __half* Ch = (__half*)Cout;
    int seg = 0, Nout = N, col_base = bn * 128;
    if (EPI == 4) {
        seg = bn >> 3;
        Ch = (seg == 0) ? (__half*)Cout : (seg == 1) ? (__half*)res : (__half*)scale;
        Nout = D_DIM;
        col_base = (bn & 7) * 128;
    }
    const int row0 = bm * 128 + wm * 64 + gid;
    const int col0 = col_base + wn * 64 + 2 * tig;
    #pragma unroll
    for (int mi = 0; mi < 4; mi++) {
        #pragma unroll
        for (int ni = 0; ni < 8; ni++) {
            const int gc = col0 + ni * 8;
            #pragma unroll
            for (int h = 0; h < 2; h++) {
                const int gr = row0 + mi * 16 + h * 8;
                float v0 = acc[mi][ni][2 * h + 0];
                float v1 = acc[mi][ni][2 * h + 1];
                if (EPI == 2) {
                    const float2 rr = *reinterpret_cast<const float2*>(
                        (const float*)res + (size_t)gr * N + gc);
                    const float2 sc = *reinterpret_cast<const float2*>(
                        (const float*)scale + gc);
                    *reinterpret_cast<float2*>(Cf + (size_t)gr * N + gc) =
                        make_float2(rr.x + sc.x * v0, rr.y + sc.y * v1);
                } else if (EPI == 3) {
                    const float t0 = v0 > 0.f ? v0 : 0.5f * v0;
                    const float t1 = v1 > 0.f ? v1 : 0.5f * v1;
                    const __half2 hv = __floats2half2_rn(t0 * t0, t1 * t1);
                    *reinterpret_cast<__half2*>(Ch + (size_t)gr * N + gc) = hv;
                } else if (EPI == 4) {
                    if (seg == 2) {
                        v0 = 1.f / (1.f + expf(-v0));
                        v1 = 1.f / (1.f + expf(-v1));
                    }
                    const __half2 hv = __floats2half2_rn(v0, v1);
                    *reinterpret_cast<__half2*>(Ch + (size_t)gr * Nout + gc) = hv;
                }
            }
        }
    }
#undef LOAD_STAGE
}

// ---------------------------------------------------------------------------
// Launch
// ---------------------------------------------------------------------------
extern "C" void kernel_launch(void* const* d_in, const int* in_sizes, int n_in,
                              void* d_out, int out_size) {
    const float* x     = (const float*)d_in[0];
    const float* Wk    = (const float*)d_in[1];
    const float* Wv    = (const float*)d_in[2];
    const float* Wr    = (const float*)d_in[3];
    const float* Wo    = (const float*)d_in[4];
    const float* td    = (const float*)d_in[5];
    const float* tfst  = (const float*)d_in[6];
    const float* mscl  = (const float*)d_in[7];
    const float* Wfc   = (const float*)d_in[8];
    const float* Wmlp  = (const float*)d_in[9];
    const float* pscl  = (const float*)d_in[10];
    float* out = (float*)d_out;

    float *p_x1;
    __half *p_normed, *p_k, *p_v, *p_r, *p_a, *p_h2, *p_w;
    cudaGetSymbolAddress((void**)&p_normed, g_normed);
    cudaGetSymbolAddress((void**)&p_k, g_k);
    cudaGetSymbolAddress((void**)&p_v, g_v);
    cudaGetSymbolAddress((void**)&p_r, g_r);
    cudaGetSymbolAddress((void**)&p_a, g_a);
    cudaGetSymbolAddress((void**)&p_x1, g_x1);
    cudaGetSymbolAddress((void**)&p_h2, g_h2);
    cudaGetSymbolAddress((void**)&p_w, g_wh);

    __half* cWkvr = p_w;                                  // [3072,1024]
    __half* cWo   = p_w + (size_t)3 * 1024 * 1024;
    __half* cWfc  = p_w + (size_t)4 * 1024 * 1024;
    __half* cWmlp = p_w + (size_t)8 * 1024 * 1024;

    cudaFuncSetAttribute(gemm_h<2>, cudaFuncAttributeMaxDynamicSharedMemorySize, SMEM_TOTAL);
    cudaFuncSetAttribute(gemm_h<3>, cudaFuncAttributeMaxDynamicSharedMemorySize, SMEM_TOTAL);
    cudaFuncSetAttribute(gemm_h<4>, cudaFuncAttributeMaxDynamicSharedMemorySize, SMEM_TOTAL);

    const dim3 gemmD(D_DIM / 128, M_ROWS / 128);        // (8, 128)
    const dim3 gemmKVR(3 * D_DIM / 128, M_ROWS / 128);  // (24, 128)
    const dim3 gemmH(H_DIM / 128, M_ROWS / 128);        // (32, 128)

    // 0) weights -> fp16 (one launch, 4 float4/thread)
    cvt_all_kernel<<<(12 * 1024 * 1024 / 4) / 1024, 256>>>(Wk, Wv, Wr, Wo, Wfc, Wmlp);
    // 1) RMS(x) -> fp16
    rms_kernel<<<M_ROWS / 8, 256>>>(x, p_normed);
    // 2) merged k|v|r GEMM (fp16 outputs)
    gemm_h<4><<<gemmKVR, 128, SMEM_TOTAL>>>(p_normed, cWkvr, p_k, D_DIM, 3 * D_DIM, p_v, p_r);
    // 3) chunked RWKV scan (fp32 state), fuse r*wkv into g_a (fp16)
    scan_carry<<<dim3(1, CH_C, B_SZ), 256>>>(p_k, p_v, td);
    scan_combine<<<dim3(D_DIM / 256, B_SZ), 256>>>(td);
    scan_apply<<<dim3(1, CH_C, B_SZ), 256>>>(p_k, p_v, p_r, td, tfst);
    // 4) o-GEMM + residual -> x1 (f32)
    gemm_h<2><<<gemmD, 128, SMEM_TOTAL>>>(p_a, cWo, p_x1, D_DIM, D_DIM, x, mscl);
    // 5) RMS(x1) -> fp16
    rms_kernel<<<M_ROWS / 8, 256>>>(p_x1, p_normed);
    // 6) fc-GEMM with leaky(0.5)^2 epilogue -> h2 (fp16)
    gemm_h<3><<<gemmH, 128, SMEM_TOTAL>>>(p_normed, cWfc, p_h2, D_DIM, H_DIM, nullptr, nullptr);
    // 7) mlp-GEMM + residual -> out (f32)
    gemm_h<2><<<gemmD, 128, SMEM_TOTAL>>>(p_h2, cWmlp, out, H_DIM, D_DIM, p_x1, pscl);
}